// round 15
// baseline (speedup 1.0000x reference)
#include <cuda_runtime.h>
#include <math.h>

#define BATCH 4096
#define NNEG 64
#define DIM 128
#define HID 512
#define MARGINF 24.0f
#define MROWS 32                     // grid 128 -> W1 LTS traffic 32 MB

// Scratch (__device__ globals; overwritten every replay, no zeroing needed).
__device__ float g_conf[BATCH];
__device__ float g_dpos[BATCH];
__device__ float g_negsp[BATCH];

__device__ __forceinline__ float warp_sum(float v) {
#pragma unroll
    for (int o = 16; o; o >>= 1) v += __shfl_xor_sync(0xffffffffu, v, o);
    return v;
}

// stable softplus(z) = max(z,0) + log1p(exp(-|z|));  -log_sigmoid(x) = softplus(-x)
__device__ __forceinline__ float softplusf(float z) {
    return fmaxf(z, 0.f) + log1pf(expf(-fabsf(z)));
}

__device__ __forceinline__ unsigned long long bcast2(float x) {
    unsigned long long r;
    asm("mov.b64 %0, {%1, %1};" : "=l"(r) : "f"(x));
    return r;
}
__device__ __forceinline__ void fma2(unsigned long long& d,
                                     unsigned long long a, unsigned long long b) {
    asm("fma.rn.f32x2 %0, %1, %2, %3;" : "=l"(d) : "l"(a), "l"(b), "l"(d));
}
__device__ __forceinline__ float2 unpack2(unsigned long long v) {
    float2 f;
    asm("mov.b64 {%0, %1}, %2;" : "=f"(f.x), "=f"(f.y) : "l"(v));
    return f;
}

// ---------------------------------------------------------------------------
// MLP / positive kernel: ROW-PACKED FFMA2 + deep W prefetch (R14-proven).
// ---------------------------------------------------------------------------
__global__ __launch_bounds__(256, 2) void mlp_pos_kernel(
    const int* __restrict__ pos, const float* __restrict__ ent,
    const float* __restrict__ rel, const float* __restrict__ W1,
    const float* __restrict__ b1, const float* __restrict__ W2,
    const float* __restrict__ b2, float* __restrict__ out)
{
    __shared__ float shA[DIM][36];      // [k][row], pitch 36 floats (16B-mult)
    __shared__ int   sh_idx[MROWS][3];
    __shared__ float sh_part[8][MROWS];

    const int tid  = threadIdx.x;
    const int lane = tid & 31;
    const int wid  = tid >> 5;          // 0..7
    const int row0 = blockIdx.x * MROWS;

    if (blockIdx.x == 0 && tid == 0) out[0] = 0.f;

    if (tid < MROWS * 3)
        sh_idx[tid / 3][tid % 3] = pos[(row0 + tid / 3) * 3 + (tid % 3)];
    __syncthreads();

    // gather + diff: consecutive tid -> consecutive k (coalesced 512B per row)
#pragma unroll
    for (int s = tid; s < MROWS * DIM; s += 256) {
        int row = s >> 7, k = s & 127;
        size_t h = (size_t)sh_idx[row][0];
        int    r = sh_idx[row][1];
        size_t t = (size_t)sh_idx[row][2];
        shA[k][row] = ent[h * DIM + k] + rel[(size_t)r * DIM + k] - ent[t * DIM + k];
    }
    __syncthreads();

    // d_pos: warp wid -> rows wid*4..+3
#pragma unroll
    for (int rr = 0; rr < 4; rr++) {
        int row = wid * 4 + rr;
        float s = 0.f;
#pragma unroll
        for (int kk = 0; kk < 4; kk++) s += fabsf(shA[lane + kk * 32][row]);
        s = warp_sum(s);
        if (lane == 0) g_dpos[row0 + row] = s;
    }

    // GEMM: accA = col 2*tid over 16 row-pairs, accB = col 2*tid+1
    unsigned long long accA[16], accB[16];
#pragma unroll
    for (int p = 0; p < 16; p++) { accA[p] = 0ull; accB[p] = 0ull; }

    const unsigned long long* Wp = (const unsigned long long*)W1;  // row k = 256 ull

    // software-pipelined W prefetch, unroll 8
    unsigned long long wcur = __ldcs(Wp + tid);
#pragma unroll 8
    for (int k = 0; k < DIM; k++) {
        unsigned long long wnext = (k + 1 < DIM)
            ? __ldcs(Wp + (size_t)(k + 1) * (HID / 2) + tid) : 0ull;
        float2 wf = unpack2(wcur);
        unsigned long long wA = bcast2(wf.x);
        unsigned long long wB = bcast2(wf.y);
#pragma unroll
        for (int q = 0; q < 8; q++) {
            // broadcast LDS.128: rows q*4..q*4+3 = two packed row-pairs
            ulonglong2 a = *(const ulonglong2*)&shA[k][q * 4];
            fma2(accA[q * 2],     a.x, wA);
            fma2(accA[q * 2 + 1], a.y, wA);
            fma2(accB[q * 2],     a.x, wB);
            fma2(accB[q * 2 + 1], a.y, wB);
        }
        wcur = wnext;
    }

    // epilogue: relu(acc + b1) * W2 over the 2 cols, warp-reduce per row
    const float2 bj = __ldcs((const float2*)b1 + tid);
    const float2 w2 = __ldcs((const float2*)W2 + tid);

#pragma unroll
    for (int p = 0; p < 16; p++) {
        float2 uA = unpack2(accA[p]);
        float2 uB = unpack2(accB[p]);
        float s0 = fmaxf(uA.x + bj.x, 0.f) * w2.x + fmaxf(uB.x + bj.y, 0.f) * w2.y;
        float s1 = fmaxf(uA.y + bj.x, 0.f) * w2.x + fmaxf(uB.y + bj.y, 0.f) * w2.y;
        s0 = warp_sum(s0);
        s1 = warp_sum(s1);
        if (lane == 0) { sh_part[wid][p * 2] = s0; sh_part[wid][p * 2 + 1] = s1; }
    }
    __syncthreads();
    if (tid < MROWS) {
        float s = b2[0];
#pragma unroll
        for (int w = 0; w < 8; w++) s += sh_part[w][tid];
        g_conf[row0 + tid] = 1.f / (1.f + expf(-s));
    }
}

// ---------------------------------------------------------------------------
// Negative kernel: SHUFFLE-FREE GATHER LOOP. Warp owns 8 contiguous negs;
// each lane accumulates its PRIVATE 4-element partial per neg into d[8]
// (independent FADD chains -> ptxas can pipeline loads across steps).
// ALL cross-lane reductions (8 warp_sums) + 8 softplus run once at the end.
// Gathers stay warp-coalesced 512B rows (R10 lesson).
// ---------------------------------------------------------------------------
__global__ __launch_bounds__(256, 8) void neg_kernel(
    const int* __restrict__ negt, const float* __restrict__ ent,
    const float* __restrict__ rel)
{
    const int b    = blockIdx.x;
    const int lane = threadIdx.x & 31;
    const int wid  = threadIdx.x >> 5;
    __shared__ float sh[8];

    // one coalesced load of this warp's 24 indices (negs wid*8 .. wid*8+7)
    int myidx = 0;
    if (lane < 24)
        myidx = __ldg(negt + (b * NNEG + wid * 8) * 3 + lane);

    float d[8];
#pragma unroll
    for (int u = 0; u < 4; u++) {
        const int i0 = u * 2, i1 = u * 2 + 1;
        int h0 = __shfl_sync(0xffffffffu, myidx, i0 * 3);
        int r0 = __shfl_sync(0xffffffffu, myidx, i0 * 3 + 1);
        int t0 = __shfl_sync(0xffffffffu, myidx, i0 * 3 + 2);
        int h1 = __shfl_sync(0xffffffffu, myidx, i1 * 3);
        int r1 = __shfl_sync(0xffffffffu, myidx, i1 * 3 + 1);
        int t1 = __shfl_sync(0xffffffffu, myidx, i1 * 3 + 2);

        float4 a0 = __ldg((const float4*)(ent + (size_t)h0 * DIM) + lane);
        float4 c0 = __ldg((const float4*)(ent + (size_t)t0 * DIM) + lane);
        float4 a1 = __ldg((const float4*)(ent + (size_t)h1 * DIM) + lane);
        float4 c1 = __ldg((const float4*)(ent + (size_t)t1 * DIM) + lane);
        float4 q0 = __ldg((const float4*)(rel + (size_t)r0 * DIM) + lane);
        float4 q1 = __ldg((const float4*)(rel + (size_t)r1 * DIM) + lane);

        // private per-lane partials, NO shuffles in the loop
        d[i0] = fabsf(a0.x + q0.x - c0.x) + fabsf(a0.y + q0.y - c0.y)
              + fabsf(a0.z + q0.z - c0.z) + fabsf(a0.w + q0.w - c0.w);
        d[i1] = fabsf(a1.x + q1.x - c1.x) + fabsf(a1.y + q1.y - c1.y)
              + fabsf(a1.z + q1.z - c1.z) + fabsf(a1.w + q1.w - c1.w);
    }

    // deferred: 8 warp reductions + 8 softplus chains, all overlapping
    float local = 0.f;
#pragma unroll
    for (int i = 0; i < 8; i++) {
        float s = warp_sum(d[i]);
        local += softplusf(s - MARGINF);
    }

    if (lane == 0) sh[wid] = local;
    __syncthreads();
    if (threadIdx.x == 0) {
        float t = 0.f;
#pragma unroll
        for (int w = 0; w < 8; w++) t += sh[w];
        g_negsp[b] = t;
    }
}

// ---------------------------------------------------------------------------
// Final combine: 8 blocks x 512 threads, one row/thread, double block-reduce,
// atomicAdd into out[0] (zeroed by mlp block 0).
// ---------------------------------------------------------------------------
__global__ __launch_bounds__(512, 2) void final_kernel(float* __restrict__ out)
{
    __shared__ double sh[16];
    const int tid = threadIdx.x;
    const int i = blockIdx.x * 512 + tid;

    float pt = softplusf(g_dpos[i] - MARGINF);       // -log_sigmoid(M - d_pos)
    float nt = -g_negsp[i] * (1.f / NNEG);           // mean log_sigmoid(M - d_neg)
    double local = (double)(g_conf[i] * (pt + nt));

#pragma unroll
    for (int o = 16; o; o >>= 1) local += __shfl_xor_sync(0xffffffffu, local, o);
    const int lane = tid & 31, wid = tid >> 5;
    if (lane == 0) sh[wid] = local;
    __syncthreads();
    if (tid < 16) {
        double v = sh[tid];
#pragma unroll
        for (int o = 8; o; o >>= 1) v += __shfl_xor_sync(0x0000ffffu, v, o);
        if (tid == 0) atomicAdd(out, (float)v);
    }
}

// ---------------------------------------------------------------------------
// Fork/join overlap. mlp launched first (R13 lesson: node order controls
// block placement; neg's 4096 blocks would otherwise starve mlp).
// ---------------------------------------------------------------------------
extern "C" void kernel_launch(void* const* d_in, const int* in_sizes, int n_in,
                              void* d_out, int out_size)
{
    static cudaStream_t s2 = nullptr;
    static cudaEvent_t evFork = nullptr, evJoin = nullptr;
    if (s2 == nullptr) {
        cudaStreamCreateWithFlags(&s2, cudaStreamNonBlocking);
        cudaEventCreateWithFlags(&evFork, cudaEventDisableTiming);
        cudaEventCreateWithFlags(&evJoin, cudaEventDisableTiming);
    }

    const int* pos = (const int*)d_in[0];
    const int* neg = (const int*)d_in[1];
    const int o = (n_in >= 9) ? 1 : 0;   // negative_sample_size scalar slot
    const float* ent = (const float*)d_in[2 + o];
    const float* rel = (const float*)d_in[3 + o];
    const float* W1  = (const float*)d_in[4 + o];
    const float* b1  = (const float*)d_in[5 + o];
    const float* W2  = (const float*)d_in[6 + o];
    const float* b2  = (const float*)d_in[7 + o];
    float* out = (float*)d_out;

    // fork: side stream inherits capture via event wait
    cudaEventRecord(evFork, 0);
    cudaStreamWaitEvent(s2, evFork, 0);

    mlp_pos_kernel<<<BATCH / MROWS, 256, 0, s2>>>(pos, ent, rel, W1, b1, W2, b2, out);
    cudaEventRecord(evJoin, s2);

    neg_kernel<<<BATCH, 256>>>(neg, ent, rel);   // overlaps mlp

    // join, then combine
    cudaStreamWaitEvent(0, evJoin, 0);
    final_kernel<<<8, 512>>>(out);
}

// round 16
// speedup vs baseline: 1.0200x; 1.0200x over previous
#include <cuda_runtime.h>
#include <math.h>

#define BATCH 4096
#define NNEG 64
#define DIM 128
#define HID 512
#define MARGINF 24.0f
#define MROWS 32                     // grid 128 -> W1 LTS traffic 32 MB

// Scratch (__device__ globals; overwritten every replay, no zeroing needed).
__device__ float g_conf[BATCH];
__device__ float g_dpos[BATCH];
__device__ float g_negsp[BATCH];

__device__ __forceinline__ float warp_sum(float v) {
#pragma unroll
    for (int o = 16; o; o >>= 1) v += __shfl_xor_sync(0xffffffffu, v, o);
    return v;
}

// stable softplus(z) = max(z,0) + log1p(exp(-|z|));  -log_sigmoid(x) = softplus(-x)
__device__ __forceinline__ float softplusf(float z) {
    return fmaxf(z, 0.f) + log1pf(expf(-fabsf(z)));
}

__device__ __forceinline__ unsigned long long bcast2(float x) {
    unsigned long long r;
    asm("mov.b64 %0, {%1, %1};" : "=l"(r) : "f"(x));
    return r;
}
__device__ __forceinline__ void fma2(unsigned long long& d,
                                     unsigned long long a, unsigned long long b) {
    asm("fma.rn.f32x2 %0, %1, %2, %3;" : "=l"(d) : "l"(a), "l"(b), "l"(d));
}
__device__ __forceinline__ float2 unpack2(unsigned long long v) {
    float2 f;
    asm("mov.b64 {%0, %1}, %2;" : "=f"(f.x), "=f"(f.y) : "l"(v));
    return f;
}

// ---------------------------------------------------------------------------
// MLP / positive kernel: ROW-PACKED FFMA2 + DEPTH-2 W prefetch.
// 128 blocks x 256 threads (1 block/SM; no min-blocks reg clamp so the
// deeper pipeline doesn't spill). W1 via __ldg (L2-reused by all blocks --
// __ldcs risked evicting it under the gather flood, see R16 analysis).
// ---------------------------------------------------------------------------
__global__ __launch_bounds__(256) void mlp_pos_kernel(
    const int* __restrict__ pos, const float* __restrict__ ent,
    const float* __restrict__ rel, const float* __restrict__ W1,
    const float* __restrict__ b1, const float* __restrict__ W2,
    const float* __restrict__ b2, float* __restrict__ out)
{
    __shared__ float shA[DIM][36];      // [k][row], pitch 36 floats (16B-mult)
    __shared__ int   sh_idx[MROWS][3];
    __shared__ float sh_part[8][MROWS];

    const int tid  = threadIdx.x;
    const int lane = tid & 31;
    const int wid  = tid >> 5;          // 0..7
    const int row0 = blockIdx.x * MROWS;

    if (blockIdx.x == 0 && tid == 0) out[0] = 0.f;

    if (tid < MROWS * 3)
        sh_idx[tid / 3][tid % 3] = pos[(row0 + tid / 3) * 3 + (tid % 3)];
    __syncthreads();

    // gather + diff: consecutive tid -> consecutive k (coalesced 512B per row)
#pragma unroll
    for (int s = tid; s < MROWS * DIM; s += 256) {
        int row = s >> 7, k = s & 127;
        size_t h = (size_t)sh_idx[row][0];
        int    r = sh_idx[row][1];
        size_t t = (size_t)sh_idx[row][2];
        shA[k][row] = ent[h * DIM + k] + rel[(size_t)r * DIM + k] - ent[t * DIM + k];
    }
    __syncthreads();

    // d_pos: warp wid -> rows wid*4..+3
#pragma unroll
    for (int rr = 0; rr < 4; rr++) {
        int row = wid * 4 + rr;
        float s = 0.f;
#pragma unroll
        for (int kk = 0; kk < 4; kk++) s += fabsf(shA[lane + kk * 32][row]);
        s = warp_sum(s);
        if (lane == 0) g_dpos[row0 + row] = s;
    }

    // GEMM: accA = col 2*tid over 16 row-pairs, accB = col 2*tid+1
    unsigned long long accA[16], accB[16];
#pragma unroll
    for (int p = 0; p < 16; p++) { accA[p] = 0ull; accB[p] = 0ull; }

    const unsigned long long* Wp = (const unsigned long long*)W1;  // row k = 256 ull

    // software-pipelined W prefetch, DEPTH 2
    unsigned long long w0 = __ldg(Wp + tid);
    unsigned long long w1 = __ldg(Wp + (HID / 2) + tid);
#pragma unroll 8
    for (int k = 0; k < DIM; k++) {
        unsigned long long wnext = (k + 2 < DIM)
            ? __ldg(Wp + (size_t)(k + 2) * (HID / 2) + tid) : 0ull;
        float2 wf = unpack2(w0);
        unsigned long long wA = bcast2(wf.x);
        unsigned long long wB = bcast2(wf.y);
#pragma unroll
        for (int q = 0; q < 8; q++) {
            // broadcast LDS.128: rows q*4..q*4+3 = two packed row-pairs
            ulonglong2 a = *(const ulonglong2*)&shA[k][q * 4];
            fma2(accA[q * 2],     a.x, wA);
            fma2(accA[q * 2 + 1], a.y, wA);
            fma2(accB[q * 2],     a.x, wB);
            fma2(accB[q * 2 + 1], a.y, wB);
        }
        w0 = w1;
        w1 = wnext;
    }

    // epilogue: relu(acc + b1) * W2 over the 2 cols, warp-reduce per row
    const float2 bj = __ldg((const float2*)b1 + tid);
    const float2 w2 = __ldg((const float2*)W2 + tid);

#pragma unroll
    for (int p = 0; p < 16; p++) {
        float2 uA = unpack2(accA[p]);
        float2 uB = unpack2(accB[p]);
        float s0 = fmaxf(uA.x + bj.x, 0.f) * w2.x + fmaxf(uB.x + bj.y, 0.f) * w2.y;
        float s1 = fmaxf(uA.y + bj.x, 0.f) * w2.x + fmaxf(uB.y + bj.y, 0.f) * w2.y;
        s0 = warp_sum(s0);
        s1 = warp_sum(s1);
        if (lane == 0) { sh_part[wid][p * 2] = s0; sh_part[wid][p * 2 + 1] = s1; }
    }
    __syncthreads();
    if (tid < MROWS) {
        float s = b2[0];
#pragma unroll
        for (int w = 0; w < 8; w++) s += sh_part[w][tid];
        g_conf[row0 + tid] = 1.f / (1.f + expf(-s));
    }
}

// ---------------------------------------------------------------------------
// Negative kernel (R15): shuffle-free gather loop, warp-coalesced 512B rows,
// private per-lane partials, deferred warp reductions + softplus.
// At the random-access DRAM ceiling (~5.4 TB/s) -- do not touch.
// ---------------------------------------------------------------------------
__global__ __launch_bounds__(256, 8) void neg_kernel(
    const int* __restrict__ negt, const float* __restrict__ ent,
    const float* __restrict__ rel)
{
    const int b    = blockIdx.x;
    const int lane = threadIdx.x & 31;
    const int wid  = threadIdx.x >> 5;
    __shared__ float sh[8];

    // one coalesced load of this warp's 24 indices (negs wid*8 .. wid*8+7)
    int myidx = 0;
    if (lane < 24)
        myidx = __ldg(negt + (b * NNEG + wid * 8) * 3 + lane);

    float d[8];
#pragma unroll
    for (int u = 0; u < 4; u++) {
        const int i0 = u * 2, i1 = u * 2 + 1;
        int h0 = __shfl_sync(0xffffffffu, myidx, i0 * 3);
        int r0 = __shfl_sync(0xffffffffu, myidx, i0 * 3 + 1);
        int t0 = __shfl_sync(0xffffffffu, myidx, i0 * 3 + 2);
        int h1 = __shfl_sync(0xffffffffu, myidx, i1 * 3);
        int r1 = __shfl_sync(0xffffffffu, myidx, i1 * 3 + 1);
        int t1 = __shfl_sync(0xffffffffu, myidx, i1 * 3 + 2);

        float4 a0 = __ldg((const float4*)(ent + (size_t)h0 * DIM) + lane);
        float4 c0 = __ldg((const float4*)(ent + (size_t)t0 * DIM) + lane);
        float4 a1 = __ldg((const float4*)(ent + (size_t)h1 * DIM) + lane);
        float4 c1 = __ldg((const float4*)(ent + (size_t)t1 * DIM) + lane);
        float4 q0 = __ldg((const float4*)(rel + (size_t)r0 * DIM) + lane);
        float4 q1 = __ldg((const float4*)(rel + (size_t)r1 * DIM) + lane);

        // private per-lane partials, NO shuffles in the loop
        d[i0] = fabsf(a0.x + q0.x - c0.x) + fabsf(a0.y + q0.y - c0.y)
              + fabsf(a0.z + q0.z - c0.z) + fabsf(a0.w + q0.w - c0.w);
        d[i1] = fabsf(a1.x + q1.x - c1.x) + fabsf(a1.y + q1.y - c1.y)
              + fabsf(a1.z + q1.z - c1.z) + fabsf(a1.w + q1.w - c1.w);
    }

    // deferred: 8 warp reductions + 8 softplus chains, all overlapping
    float local = 0.f;
#pragma unroll
    for (int i = 0; i < 8; i++) {
        float s = warp_sum(d[i]);
        local += softplusf(s - MARGINF);
    }

    if (lane == 0) sh[wid] = local;
    __syncthreads();
    if (threadIdx.x == 0) {
        float t = 0.f;
#pragma unroll
        for (int w = 0; w < 8; w++) t += sh[w];
        g_negsp[b] = t;
    }
}

// ---------------------------------------------------------------------------
// Final combine: 8 blocks x 512 threads, one row/thread, double block-reduce,
// atomicAdd into out[0] (zeroed by mlp block 0).
// ---------------------------------------------------------------------------
__global__ __launch_bounds__(512, 2) void final_kernel(float* __restrict__ out)
{
    __shared__ double sh[16];
    const int tid = threadIdx.x;
    const int i = blockIdx.x * 512 + tid;

    float pt = softplusf(g_dpos[i] - MARGINF);       // -log_sigmoid(M - d_pos)
    float nt = -g_negsp[i] * (1.f / NNEG);           // mean log_sigmoid(M - d_neg)
    double local = (double)(g_conf[i] * (pt + nt));

#pragma unroll
    for (int o = 16; o; o >>= 1) local += __shfl_xor_sync(0xffffffffu, local, o);
    const int lane = tid & 31, wid = tid >> 5;
    if (lane == 0) sh[wid] = local;
    __syncthreads();
    if (tid < 16) {
        double v = sh[tid];
#pragma unroll
        for (int o = 8; o; o >>= 1) v += __shfl_xor_sync(0x0000ffffu, v, o);
        if (tid == 0) atomicAdd(out, (float)v);
    }
}

// ---------------------------------------------------------------------------
// Fork/join overlap. mlp launched first (R13 lesson: node order controls
// block placement; neg's 4096 blocks would otherwise starve mlp).
// ---------------------------------------------------------------------------
extern "C" void kernel_launch(void* const* d_in, const int* in_sizes, int n_in,
                              void* d_out, int out_size)
{
    static cudaStream_t s2 = nullptr;
    static cudaEvent_t evFork = nullptr, evJoin = nullptr;
    if (s2 == nullptr) {
        cudaStreamCreateWithFlags(&s2, cudaStreamNonBlocking);
        cudaEventCreateWithFlags(&evFork, cudaEventDisableTiming);
        cudaEventCreateWithFlags(&evJoin, cudaEventDisableTiming);
    }

    const int* pos = (const int*)d_in[0];
    const int* neg = (const int*)d_in[1];
    const int o = (n_in >= 9) ? 1 : 0;   // negative_sample_size scalar slot
    const float* ent = (const float*)d_in[2 + o];
    const float* rel = (const float*)d_in[3 + o];
    const float* W1  = (const float*)d_in[4 + o];
    const float* b1  = (const float*)d_in[5 + o];
    const float* W2  = (const float*)d_in[6 + o];
    const float* b2  = (const float*)d_in[7 + o];
    float* out = (float*)d_out;

    // fork: side stream inherits capture via event wait
    cudaEventRecord(evFork, 0);
    cudaStreamWaitEvent(s2, evFork, 0);

    mlp_pos_kernel<<<BATCH / MROWS, 256, 0, s2>>>(pos, ent, rel, W1, b1, W2, b2, out);
    cudaEventRecord(evJoin, s2);

    neg_kernel<<<BATCH, 256>>>(neg, ent, rel);   // overlaps mlp

    // join, then combine
    cudaStreamWaitEvent(0, evJoin, 0);
    final_kernel<<<8, 512>>>(out);
}